// round 3
// baseline (speedup 1.0000x reference)
#include <cuda_runtime.h>
#include <cuda_bf16.h>
#include <cstdint>

// Embedding gather: out[i, :] = embeddings[x[i], :]
// x: int32 [8192], embeddings: fp32 [32000, 1024], out: fp32 [8192, 1024]
//
// Pure-DMA design: each 4KB row is moved GMEM->SMEM->GMEM via cp.async.bulk
// (TMA 1D bulk copies). 10-stage SMEM ring, load-ahead 7, 1 warp per CTA,
// 2 CTAs per SM -> ~56KB of reads continuously in flight per SM.

static constexpr int EMBED_DIM  = 1024;
static constexpr int ROW_BYTES  = EMBED_DIM * 4;   // 4096
static constexpr int N_ROWS     = 8192;
static constexpr int GRID       = 296;             // 2 CTAs per SM (148 SMs)
static constexpr int NSTAGES    = 10;              // 40KB ring (static smem)
static constexpr int LOAD_AHEAD = 7;               // loads in flight
static constexpr int WG_KEEP    = NSTAGES - LOAD_AHEAD;  // 3 stores outstanding
static constexpr int MAX_ROWS_PER_CTA = (N_ROWS + GRID - 1) / GRID;  // 28

static __device__ __forceinline__ uint32_t s2u(const void* p) {
    return (uint32_t)__cvta_generic_to_shared(p);
}

static __device__ __forceinline__ void mbar_init(uint32_t mbar, uint32_t count) {
    asm volatile("mbarrier.init.shared.b64 [%0], %1;" :: "r"(mbar), "r"(count) : "memory");
}

static __device__ __forceinline__ void mbar_expect_tx(uint32_t mbar, uint32_t bytes) {
    asm volatile("mbarrier.arrive.expect_tx.shared.b64 _, [%0], %1;"
                 :: "r"(mbar), "r"(bytes) : "memory");
}

static __device__ __forceinline__ void mbar_wait(uint32_t mbar, uint32_t parity) {
    uint32_t done;
    asm volatile(
        "{\n\t"
        ".reg .pred p;\n\t"
        "mbarrier.try_wait.parity.shared.b64 p, [%1], %2;\n\t"
        "selp.b32 %0, 1, 0, p;\n\t"
        "}"
        : "=r"(done) : "r"(mbar), "r"(parity) : "memory");
    if (!done) {
        asm volatile(
            "{\n\t"
            ".reg .pred P1;\n\t"
            "WAIT_LOOP_%=:\n\t"
            "mbarrier.try_wait.parity.shared.b64 P1, [%0], %1, 0x989680;\n\t"
            "@P1 bra.uni WAIT_DONE_%=;\n\t"
            "bra.uni WAIT_LOOP_%=;\n\t"
            "WAIT_DONE_%=:\n\t"
            "}"
            :: "r"(mbar), "r"(parity) : "memory");
    }
}

static __device__ __forceinline__ void bulk_g2s(uint32_t dst_smem, const void* src_gmem,
                                                uint32_t bytes, uint32_t mbar) {
    asm volatile(
        "cp.async.bulk.shared::cluster.global.mbarrier::complete_tx::bytes "
        "[%0], [%1], %2, [%3];"
        :: "r"(dst_smem), "l"(src_gmem), "r"(bytes), "r"(mbar) : "memory");
}

static __device__ __forceinline__ void bulk_s2g(void* dst_gmem, uint32_t src_smem,
                                                uint32_t bytes) {
    asm volatile(
        "cp.async.bulk.global.shared::cta.bulk_group [%0], [%1], %2;"
        :: "l"(dst_gmem), "r"(src_smem), "r"(bytes) : "memory");
}

__global__ __launch_bounds__(32, 2)
void embedding_dma_kernel(const int* __restrict__ idx,
                          const float* __restrict__ emb,
                          float* __restrict__ out)
{
    __shared__ alignas(128) char buf[NSTAGES * ROW_BYTES];
    __shared__ alignas(8)  uint64_t mbar[NSTAGES];
    __shared__ int sidx[MAX_ROWS_PER_CTA];

    const int bid = blockIdx.x;
    const int t   = threadIdx.x;

    // Stage this CTA's indices into SMEM (one LDG per row, off critical path)
    if (t < MAX_ROWS_PER_CTA) {
        int row = bid + GRID * t;
        if (row < N_ROWS) sidx[t] = idx[row];
    }

    if (t == 0) {
        for (int s = 0; s < NSTAGES; s++)
            mbar_init(s2u(&mbar[s]), 1);
        asm volatile("fence.proxy.async.shared::cta;" ::: "memory");
    }
    __syncwarp();

    if (t != 0) return;   // single orchestrator thread

    // Number of rows for this CTA
    int n = (N_ROWS - bid + GRID - 1) / GRID;

    const uint32_t buf_base  = s2u(buf);
    const uint32_t mbar_base = s2u(&mbar[0]);

    // Prologue: fill the pipeline with LOAD_AHEAD loads
    int pro = n < LOAD_AHEAD ? n : LOAD_AHEAD;
    for (int k = 0; k < pro; k++) {
        const int s = k;  // k < NSTAGES
        const uint32_t mb = mbar_base + s * 8;
        mbar_expect_tx(mb, ROW_BYTES);
        bulk_g2s(buf_base + s * ROW_BYTES,
                 emb + (size_t)sidx[k] * EMBED_DIM, ROW_BYTES, mb);
    }

    // Main loop
    for (int k = 0; k < n; k++) {
        const int s  = k % NSTAGES;
        const int ph = (k / NSTAGES) & 1;

        mbar_wait(mbar_base + s * 8, ph);

        const int row = bid + GRID * k;
        bulk_s2g(out + (size_t)row * EMBED_DIM, buf_base + s * ROW_BYTES, ROW_BYTES);
        asm volatile("cp.async.bulk.commit_group;" ::: "memory");

        const int kn = k + LOAD_AHEAD;
        if (kn < n) {
            // Stage (kn % NSTAGES) was last used by row kn-NSTAGES whose store
            // is commit-group k-WG_KEEP; wait_group.read WG_KEEP guarantees it
            // has finished reading SMEM.
            asm volatile("cp.async.bulk.wait_group.read %0;" :: "n"(WG_KEEP) : "memory");
            const int sn = kn % NSTAGES;
            const uint32_t mb = mbar_base + sn * 8;
            mbar_expect_tx(mb, ROW_BYTES);
            bulk_g2s(buf_base + sn * ROW_BYTES,
                     emb + (size_t)sidx[kn] * EMBED_DIM, ROW_BYTES, mb);
        }
    }

    // Drain all outstanding stores before exit
    asm volatile("cp.async.bulk.wait_group %0;" :: "n"(0) : "memory");
}

extern "C" void kernel_launch(void* const* d_in, const int* in_sizes, int n_in,
                              void* d_out, int out_size)
{
    const int*   x   = (const int*)d_in[0];          // [4, 2048] int32 indices
    const float* emb = (const float*)d_in[1];        // [32000, 1024] fp32
    float*       out = (float*)d_out;                // [4, 2048, 1024] fp32

    embedding_dma_kernel<<<GRID, 32>>>(x, emb, out);
}